// round 3
// baseline (speedup 1.0000x reference)
#include <cuda_runtime.h>
#include <cuda_bf16.h>

// Problem constants (fixed by the dataset)
#define B 8
#define L 2048
#define H 1024
#define C 64
#define RPB 8                      // rows per block (one warp per row)
#define GRID (B * L / RPB)         // 2048 blocks
#define BPB (L / RPB)              // 256 blocks per batch

// Persistent scratch (zero-initialized at module load; self-reset each launch)
__device__ float        g_acc[B * C];
__device__ unsigned int g_count;

// ---------------------------------------------------------------------------
// Fused kernel:
//  1) proj[row] = dot(feature[row,:], w)      (DRAM-bound, 64 MB read)
//  2) scatter proj into per-span accumulators via one atomicAdd per
//     (block, overlapping span)
//  3) last-arriving block finalizes: out = acc/count + bias, resets scratch
// ---------------------------------------------------------------------------
__global__ __launch_bounds__(256) void fused_kernel(
    const float* __restrict__ feature,       // [B*L, H]
    const float* __restrict__ fc_weight,     // [H]
    const float* __restrict__ fc_bias,       // [1]
    const int*   __restrict__ position_list, // [B*C*2]
    float* __restrict__ out)                 // [B*C]
{
    __shared__ float sw[H];
    __shared__ float sproj[RPB];
    __shared__ int   s_src[C], s_end[C];
    __shared__ bool  is_last;

    const int tid   = threadIdx.x;
    const int blk   = blockIdx.x;
    const int batch = blk >> 8;              // blk / BPB
    const int row0  = (blk & (BPB - 1)) * RPB;

    // Stage weights (4 KB) and this batch's spans (512 B) into smem
    #pragma unroll
    for (int i = tid; i < H; i += 256) sw[i] = fc_weight[i];
    if (tid < C) {
        const int si = (batch * C + tid) * 2;
        s_src[tid] = position_list[si + 0];
        s_end[tid] = position_list[si + 1];
    }
    __syncthreads();

    // --- Stage 1: projection, one warp per row ---
    const int warp = tid >> 5;
    const int lane = tid & 31;
    const int row  = blk * RPB + warp;       // global row 0..B*L-1

    const float4* __restrict__ f4 = reinterpret_cast<const float4*>(
        feature + (size_t)row * H);
    const float4* __restrict__ w4 = reinterpret_cast<const float4*>(sw);

    float acc = 0.0f;
    #pragma unroll
    for (int i = 0; i < 8; i++) {
        const int idx = i * 32 + lane;       // 0..255 float4s
        float4 v = f4[idx];
        float4 w = w4[idx];
        acc = fmaf(v.x, w.x, acc);
        acc = fmaf(v.y, w.y, acc);
        acc = fmaf(v.z, w.z, acc);
        acc = fmaf(v.w, w.w, acc);
    }
    #pragma unroll
    for (int o = 16; o > 0; o >>= 1)
        acc += __shfl_xor_sync(0xFFFFFFFFu, acc, o);
    if (lane == 0) sproj[warp] = acc;
    __syncthreads();

    // --- Stage 2: scatter into span accumulators ---
    if (tid < C) {
        const int src = s_src[tid];
        const int end = s_end[tid];
        // overlap of [src,end] with this block's rows [row0, row0+RPB-1]
        int lo = src - row0; if (lo < 0) lo = 0;
        int hi = end - row0; if (hi > RPB - 1) hi = RPB - 1;
        if (lo <= hi) {
            float s = 0.0f;
            #pragma unroll
            for (int r = 0; r < RPB; r++)
                if (r >= lo && r <= hi) s += sproj[r];
            atomicAdd(&g_acc[batch * C + tid], s);
        }
    }

    // --- Stage 3: arrive; last block finalizes ---
    __threadfence();
    if (tid == 0) {
        unsigned int old = atomicAdd(&g_count, 1u);
        is_last = (old == GRID - 1);
    }
    __syncthreads();

    if (is_last) {
        const float bias = fc_bias[0];
        for (int i = tid; i < B * C; i += 256) {
            const int src = position_list[i * 2 + 0];
            const int end = position_list[i * 2 + 1];
            const float v = __ldcg(&g_acc[i]);       // L2-coherent read
            out[i] = v / (float)(end - src + 1) + bias;
            g_acc[i] = 0.0f;                          // reset for next launch
        }
        if (tid == 0) g_count = 0u;
    }
}

// ---------------------------------------------------------------------------
extern "C" void kernel_launch(void* const* d_in, const int* in_sizes, int n_in,
                              void* d_out, int out_size) {
    const float* feature       = (const float*)d_in[0];  // [B,L,H] f32
    const float* fc_weight     = (const float*)d_in[1];  // [1,H]   f32
    const float* fc_bias       = (const float*)d_in[2];  // [1]     f32
    const int*   position_list = (const int*)  d_in[3];  // [B,C,2] i32
    float* out = (float*)d_out;                          // [B*C,1] f32

    fused_kernel<<<GRID, 256>>>(feature, fc_weight, fc_bias,
                                position_list, out);
}

// round 4
// speedup vs baseline: 1.2864x; 1.2864x over previous
#include <cuda_runtime.h>
#include <cuda_bf16.h>

// Problem constants (fixed by the dataset)
#define B 8
#define L 2048
#define H 1024
#define C 64
#define RPB 8                      // rows per block (one warp per row)
#define GRID (B * L / RPB)         // 2048 blocks
#define BPB (L / RPB)              // 256 blocks per batch

// Persistent scratch (zero-initialized at module load; self-reset each launch)
__device__ float        g_acc[B * C];
__device__ unsigned int g_count;

// ---------------------------------------------------------------------------
// Fused kernel (fence-free):
//  1) proj[row] = dot(feature[row,:], w)      (DRAM-bound, 64 MB read)
//  2) scatter proj into per-span accumulators via value-returning atomicAdd
//     (ATOMG completes at L2 -> device-coherent; return is consumed so the
//     thread waits for completion BEFORE __syncthreads, giving release
//     ordering w.r.t. the g_count arrival with NO membar / NO CCTL.IVALL)
//  3) last-arriving block finalizes: out = acc/count + bias, resets scratch
// ---------------------------------------------------------------------------
__global__ __launch_bounds__(256) void fused_kernel(
    const float* __restrict__ feature,       // [B*L, H]
    const float* __restrict__ fc_weight,     // [H]
    const float* __restrict__ fc_bias,       // [1]
    const int*   __restrict__ position_list, // [B*C*2]
    float* __restrict__ out)                 // [B*C]
{
    __shared__ float sw[H];
    __shared__ float sproj[RPB];
    __shared__ int   s_src[C], s_end[C];
    __shared__ bool  is_last;
    __shared__ int   s_sink;                 // forces atomic-return consumption

    const int tid   = threadIdx.x;
    const int blk   = blockIdx.x;
    const int batch = blk >> 8;              // blk / BPB
    const int row0  = (blk & (BPB - 1)) * RPB;

    // Stage weights (4 KB) and this batch's spans (512 B) into smem
    #pragma unroll
    for (int i = tid; i < H; i += 256) sw[i] = fc_weight[i];
    if (tid < C) {
        const int si = (batch * C + tid) * 2;
        s_src[tid] = position_list[si + 0];
        s_end[tid] = position_list[si + 1];
    }
    __syncthreads();

    // --- Stage 1: projection, one warp per row ---
    const int warp = tid >> 5;
    const int lane = tid & 31;
    const int row  = blk * RPB + warp;       // global row 0..B*L-1

    const float4* __restrict__ f4 = reinterpret_cast<const float4*>(
        feature + (size_t)row * H);
    const float4* __restrict__ w4 = reinterpret_cast<const float4*>(sw);

    float acc = 0.0f;
    #pragma unroll
    for (int i = 0; i < 8; i++) {
        const int idx = i * 32 + lane;       // 0..255 float4s
        float4 v = f4[idx];
        float4 w = w4[idx];
        acc = fmaf(v.x, w.x, acc);
        acc = fmaf(v.y, w.y, acc);
        acc = fmaf(v.z, w.z, acc);
        acc = fmaf(v.w, w.w, acc);
    }
    #pragma unroll
    for (int o = 16; o > 0; o >>= 1)
        acc += __shfl_xor_sync(0xFFFFFFFFu, acc, o);
    if (lane == 0) sproj[warp] = acc;
    __syncthreads();

    // --- Stage 2: scatter into span accumulators (threads 0..63) ---
    if (tid < C) {
        const int src = s_src[tid];
        const int end = s_end[tid];
        // overlap of [src,end] with this block's rows [row0, row0+RPB-1]
        int lo = src - row0; if (lo < 0) lo = 0;
        int hi = end - row0; if (hi > RPB - 1) hi = RPB - 1;
        if (lo <= hi) {
            float s = 0.0f;
            #pragma unroll
            for (int r = 0; r < RPB; r++)
                if (r >= lo && r <= hi) s += sproj[r];
            // Value-returning atomic: completion at L2 is observed before we
            // can evaluate the (never-true) predicate below.
            float old = atomicAdd(&g_acc[batch * C + tid], s);
            if (__float_as_uint(old) == 0xDEADBEEFu) s_sink = 1;
        }
    }
    __syncthreads();   // all scatter atomics of this block have completed

    // --- Stage 3: arrive; last block finalizes ---
    if (tid == 0) {
        unsigned int prev = atomicAdd(&g_count, 1u);
        is_last = (prev == GRID - 1);
    }
    __syncthreads();

    if (is_last) {
        const float bias = fc_bias[0];
        #pragma unroll
        for (int k = 0; k < 2; k++) {
            const int i = tid + k * 256;     // 0..511
            const int src = position_list[i * 2 + 0];
            const int end = position_list[i * 2 + 1];
            const float v = __ldcg(&g_acc[i]);        // L2-coherent read
            out[i] = v / (float)(end - src + 1) + bias;
            __stcg(&g_acc[i], 0.0f);                  // reset for next launch
        }
        if (tid == 0) g_count = 0u;
    }
}

// ---------------------------------------------------------------------------
extern "C" void kernel_launch(void* const* d_in, const int* in_sizes, int n_in,
                              void* d_out, int out_size) {
    const float* feature       = (const float*)d_in[0];  // [B,L,H] f32
    const float* fc_weight     = (const float*)d_in[1];  // [1,H]   f32
    const float* fc_bias       = (const float*)d_in[2];  // [1]     f32
    const int*   position_list = (const int*)  d_in[3];  // [B,C,2] i32
    float* out = (float*)d_out;                          // [B*C,1] f32

    fused_kernel<<<GRID, 256>>>(feature, fc_weight, fc_bias,
                                position_list, out);
}

// round 5
// speedup vs baseline: 1.5284x; 1.1881x over previous
#include <cuda_runtime.h>
#include <cuda_bf16.h>

// Problem constants (fixed by the dataset)
#define B 8
#define L 2048
#define H 1024
#define C 64
#define RPB 32                     // rows per block (4 chunks x 8 warps)
#define GRID (B * L / RPB)         // 512 blocks
#define BPB (L / RPB)              // 64 blocks per batch

// Persistent scratch (zero-initialized at module load; self-reset each launch)
__device__ float        g_acc[B * C];
__device__ unsigned int g_count;

// ---------------------------------------------------------------------------
// Fused kernel (fence-free, epilogue amortized 4x vs R4):
//  1) 4 chunks: proj[row] = dot(feature[row,:], w), warp-per-row
//  2) scatter 32-row window into span accumulators via value-returning
//     atomicAdd (completion observed before __syncthreads -> release
//     ordering for the g_count arrival without MEMBAR/CCTL)
//  3) last-arriving block finalizes: out = acc/count + bias, resets scratch
// ---------------------------------------------------------------------------
__global__ __launch_bounds__(256) void fused_kernel(
    const float* __restrict__ feature,       // [B*L, H]
    const float* __restrict__ fc_weight,     // [H]
    const float* __restrict__ fc_bias,       // [1]
    const int*   __restrict__ position_list, // [B*C*2]
    float* __restrict__ out)                 // [B*C]
{
    __shared__ float sw[H];
    __shared__ float sproj[RPB];
    __shared__ int   s_src[C], s_end[C];
    __shared__ bool  is_last;
    __shared__ int   s_sink;                 // forces atomic-return consumption

    const int tid   = threadIdx.x;
    const int blk   = blockIdx.x;
    const int batch = blk / BPB;
    const int row0  = (blk % BPB) * RPB;

    // Stage weights (4 KB) and this batch's spans (512 B) into smem
    #pragma unroll
    for (int i = tid; i < H; i += 256) sw[i] = fc_weight[i];
    if (tid < C) {
        const int si = (batch * C + tid) * 2;
        s_src[tid] = position_list[si + 0];
        s_end[tid] = position_list[si + 1];
    }
    __syncthreads();

    const int warp = tid >> 5;
    const int lane = tid & 31;
    const float4* __restrict__ w4 = reinterpret_cast<const float4*>(sw);

    // --- Stage 1: 4 chunks of 8 rows, warp-per-row ---
    #pragma unroll
    for (int c = 0; c < 4; c++) {
        const int r   = c * 8 + warp;                    // 0..31 within block
        const int row = batch * L + row0 + r;            // global row
        const float4* __restrict__ f4 =
            reinterpret_cast<const float4*>(feature + (size_t)row * H);

        float acc = 0.0f;
        #pragma unroll
        for (int i = 0; i < 8; i++) {
            const int idx = i * 32 + lane;               // 0..255 float4s
            float4 v = f4[idx];
            float4 w = w4[idx];
            acc = fmaf(v.x, w.x, acc);
            acc = fmaf(v.y, w.y, acc);
            acc = fmaf(v.z, w.z, acc);
            acc = fmaf(v.w, w.w, acc);
        }
        #pragma unroll
        for (int o = 16; o > 0; o >>= 1)
            acc += __shfl_xor_sync(0xFFFFFFFFu, acc, o);
        if (lane == 0) sproj[r] = acc;
    }
    __syncthreads();

    // --- Stage 2: scatter into span accumulators (threads 0..63) ---
    if (tid < C) {
        const int src = s_src[tid];
        const int end = s_end[tid];
        // overlap of [src,end] with this block's rows [row0, row0+RPB-1]
        int lo = src - row0; if (lo < 0) lo = 0;
        int hi = end - row0; if (hi > RPB - 1) hi = RPB - 1;
        if (lo <= hi) {
            float s = 0.0f;
            #pragma unroll
            for (int r = 0; r < RPB; r++)
                if (r >= lo && r <= hi) s += sproj[r];
            // Value-returning atomic: L2 completion observed before the
            // (never-true) predicate below can be evaluated.
            float old = atomicAdd(&g_acc[batch * C + tid], s);
            if (__float_as_uint(old) == 0xDEADBEEFu) s_sink = 1;
        }
    }
    __syncthreads();   // all scatter atomics of this block have completed

    // --- Stage 3: arrive; last block finalizes ---
    if (tid == 0) {
        unsigned int prev = atomicAdd(&g_count, 1u);
        is_last = (prev == GRID - 1);
    }
    __syncthreads();

    if (is_last) {
        const float bias = fc_bias[0];
        #pragma unroll
        for (int k = 0; k < 2; k++) {
            const int i = tid + k * 256;     // 0..511
            const int src = position_list[i * 2 + 0];
            const int end = position_list[i * 2 + 1];
            const float v = __ldcg(&g_acc[i]);        // L2-coherent read
            out[i] = v / (float)(end - src + 1) + bias;
            __stcg(&g_acc[i], 0.0f);                  // reset for next launch
        }
        if (tid == 0) g_count = 0u;
    }
}

// ---------------------------------------------------------------------------
extern "C" void kernel_launch(void* const* d_in, const int* in_sizes, int n_in,
                              void* d_out, int out_size) {
    const float* feature       = (const float*)d_in[0];  // [B,L,H] f32
    const float* fc_weight     = (const float*)d_in[1];  // [1,H]   f32
    const float* fc_bias       = (const float*)d_in[2];  // [1]     f32
    const int*   position_list = (const int*)  d_in[3];  // [B,C,2] i32
    float* out = (float*)d_out;                          // [B*C,1] f32

    fused_kernel<<<GRID, 256>>>(feature, fc_weight, fc_bias,
                                position_list, out);
}